// round 4
// baseline (speedup 1.0000x reference)
#include <cuda_runtime.h>
#include <cstdint>

// Problem shape (fixed by the reference)
#define T_STEPS 5
#define BB 32
#define CC 128
#define HW 1024                   // 32*32
#define NPLANES (BB * CC)         // 4096 (b,c) planes
#define NPT (NPLANES * HW)        // 4,194,304 elements per timestep

#define NBLK 608                  // = 4 blocks/SM * 152 SMs; exact wave-1 capacity
#define MAXP 7                    // max planes per block: ceil(4096/608)

static constexpr float V_TH    = 0.5f;
static constexpr float W_DEC   = 0.5f;
static constexpr float LOWER_C = 0.2f - 0.03f;   // 0.17
static constexpr float UPPER_C = 0.2f + 0.03f;   // 0.23
static constexpr float EMA0    = 0.17f;

// Cross-block state (device globals — no allocation allowed)
__device__ float    g_chsum[T_STEPS - 1][CC];  // per-step spike sums
__device__ unsigned g_bar;                     // grid barrier arrive counter

__device__ __forceinline__ float sigmoidf(float x) {
    return 1.0f / (1.0f + expf(-x));
}

__global__ void lif_init() {
    if (threadIdx.x == 0) g_bar = 0u;
    for (int i = threadIdx.x; i < (T_STEPS - 1) * CC; i += blockDim.x)
        ((float*)g_chsum)[i] = 0.0f;
}

// Persistent kernel, flat plane partition (6-7 planes per block).
// Residency proof (spin barrier requires all 608 co-resident):
//   smem ~28.2KB * 4 = 113KB < 228KB;  regs <= 64 via __launch_bounds__(256,4)
//   (R3 proved capacity >= 4 at 33KB smem / same bounds);  threads 1024/SM.
__global__ __launch_bounds__(256, 4)
void lif_persistent(const float* __restrict__ xe,
                    const float* __restrict__ xi,
                    const float* __restrict__ alpha_raw,
                    const float* __restrict__ beta_raw,
                    float* __restrict__ out)
{
    __shared__ float s_mem[MAXP * HW];   // 28 KB membrane carry
    __shared__ float s_ema[MAXP];
    __shared__ float s_inhw[MAXP];
    __shared__ float s_psum[MAXP];

    const int tid  = threadIdx.x;
    const int lane = tid & 31;

    // Flat plane partition: block k owns planes [k*4096/608, (k+1)*4096/608)
    const int p0 = (int)(((long long)blockIdx.x     * NPLANES) / NBLK);
    const int p1 = (int)(((long long)(blockIdx.x+1) * NPLANES) / NBLK);
    const int np = p1 - p0;                  // 6 or 7

    // Zero membrane carry + per-block channel state
    #pragma unroll
    for (int i = 0; i < MAXP; ++i) {
        if (i >= np) break;
        *reinterpret_cast<float4*>(&s_mem[i * HW + tid * 4]) =
            make_float4(0.f, 0.f, 0.f, 0.f);
    }
    if (tid < MAXP) { s_ema[tid] = EMA0; s_inhw[tid] = 0.0f; s_psum[tid] = 0.0f; }

    const float alpha = 4.0f * sigmoidf(__ldg(alpha_raw));
    const float beta  = sigmoidf(__ldg(beta_raw));
    __syncthreads();

    for (int t = 0; t < T_STEPS; ++t) {
        const float* xet = xe  + (size_t)t * NPT;
        const float* xit = xi  + (size_t)t * NPT;
        float*       st  = out + (size_t)t * NPT;
        const bool last = (t == T_STEPS - 1);

        float cnt[MAXP];
        #pragma unroll
        for (int i = 0; i < MAXP; ++i) cnt[i] = 0.0f;

        #pragma unroll
        for (int i = 0; i < MAXP; ++i) {
            if (i >= np) break;
            const int plane = p0 + i;
            const size_t base = (size_t)plane * HW + tid * 4;
            const float bw = beta * (1.0f - s_inhw[i]);

            const float4 e4 = __ldcs(reinterpret_cast<const float4*>(xet + base));
            const float4 i4 = __ldcs(reinterpret_cast<const float4*>(xit + base));
            float4 m = *reinterpret_cast<float4*>(&s_mem[i * HW + tid * 4]);
            float4 s;

            m.x = W_DEC * m.x + e4.x / (1.0f + alpha * i4.x) - bw * i4.x;
            s.x = (m.x >= V_TH) ? 1.0f : 0.0f;  m.x -= V_TH * s.x;
            m.y = W_DEC * m.y + e4.y / (1.0f + alpha * i4.y) - bw * i4.y;
            s.y = (m.y >= V_TH) ? 1.0f : 0.0f;  m.y -= V_TH * s.y;
            m.z = W_DEC * m.z + e4.z / (1.0f + alpha * i4.z) - bw * i4.z;
            s.z = (m.z >= V_TH) ? 1.0f : 0.0f;  m.z -= V_TH * s.z;
            m.w = W_DEC * m.w + e4.w / (1.0f + alpha * i4.w) - bw * i4.w;
            s.w = (m.w >= V_TH) ? 1.0f : 0.0f;  m.w -= V_TH * s.w;

            __stcs(reinterpret_cast<float4*>(st + base), s);
            if (!last) {
                *reinterpret_cast<float4*>(&s_mem[i * HW + tid * 4]) = m;
                cnt[i] = s.x + s.y + s.z + s.w;
            }
        }

        if (!last) {
            // Per-plane spike sums: warp reduce -> smem -> one global RED each
            #pragma unroll
            for (int i = 0; i < MAXP; ++i) {
                if (i >= np) break;
                float v = cnt[i];
                #pragma unroll
                for (int off = 16; off > 0; off >>= 1)
                    v += __shfl_down_sync(0xFFFFFFFFu, v, off);
                if (lane == 0) atomicAdd(&s_psum[i], v);
            }
            __syncthreads();
            if (tid < np) {
                const int c = (p0 + tid) & (CC - 1);
                atomicAdd(&g_chsum[t][c], s_psum[tid]);   // no return use -> RED
                s_psum[tid] = 0.0f;
            }
            __syncthreads();

            // ---- grid barrier (publish atomics, then arrive+spin) ----
            if (tid == 0) {
                __threadfence();
                atomicAdd(&g_bar, 1u);
                const unsigned target = (unsigned)NBLK * (unsigned)(t + 1);
                while (*(volatile unsigned*)&g_bar < target) __nanosleep(64);
            }
            __syncthreads();

            // Per-channel EMA + inhibition update (replicated per block)
            if (tid < np) {
                const int c = (p0 + tid) & (CC - 1);
                const float sum = __ldcg(&g_chsum[t][c]);
                const float ema = 0.9f * s_ema[tid] + 0.1f * (sum * (1.0f / 32768.0f));
                s_ema[tid]  = ema;
                s_inhw[tid] = 4.0f * (sigmoidf(LOWER_C - ema) - sigmoidf(ema - UPPER_C));
            }
            __syncthreads();
        }
    }
}

extern "C" void kernel_launch(void* const* d_in, const int* in_sizes, int n_in,
                              void* d_out, int out_size)
{
    const float* xe = (const float*)d_in[0];  // x_exc  [T,B,C,H,W]
    const float* xi = (const float*)d_in[1];  // x_inh  [T,B,C,H,W]
    const float* ar = (const float*)d_in[2];  // alpha_raw scalar
    const float* br = (const float*)d_in[3];  // beta_raw scalar
    float* out = (float*)d_out;               // spikes [T,B,C,H,W]

    lif_init<<<1, 128>>>();
    lif_persistent<<<NBLK, 256>>>(xe, xi, ar, br, out);
}